// round 13
// baseline (speedup 1.0000x reference)
#include <cuda_runtime.h>
#include <math.h>
#include <stdint.h>

// ---------------------------------------------------------------------------
// Problem constants
// ---------------------------------------------------------------------------
#define BATCH  4
#define NTOK   1024
#define DMODEL 1024
#define HEADS  16
#define HDIM   64
#define ROWS   (BATCH * NTOK)     // 4096
#define MLPD   4096
#define SIXD   (6 * DMODEL)       // 6144
#define EPS    1e-6f

// ---------------------------------------------------------------------------
// Scratch (device globals: no allocations allowed)
// ---------------------------------------------------------------------------
__device__ float g_mod[BATCH * SIXD];
__device__ float g_h  [ROWS * DMODEL];      // K-permuted (GEMM A operand)
__device__ float g_q  [ROWS * DMODEL];      // natural (attention input)
__device__ float g_kv [ROWS * 2 * DMODEL];  // natural (attention input)
__device__ float g_att[ROWS * DMODEL];      // K-permuted (Wo A operand)
__device__ float g_m1 [ROWS * MLPD];        // K-permuted (W2 A operand)
// tf32-rounded, row-permuted weights; Wq|Wkv fused into [1024][3072]
__device__ float g_wqkv[DMODEL * 3 * DMODEL];
__device__ float g_wo  [DMODEL * DMODEL];
__device__ float g_w1  [DMODEL * MLPD];
__device__ float g_w2  [MLPD * DMODEL];

// ---------------------------------------------------------------------------
// Helpers
// ---------------------------------------------------------------------------
// K-dim permutation within each group of 8: j -> 2j (j<4), 2j-7 (j>=4).
// Makes mma fragment pair (k=tg, k=tg+4) adjacent in storage -> LDS.64.
__device__ __forceinline__ int kperm(int k) {
    return (k & ~7) | (((k & 3) << 1) | ((k >> 2) & 1));
}

__device__ __forceinline__ float gelu_tanh(float y) {
    float y3 = y * y * y;
    return 0.5f * y * (1.0f + tanhf(0.7978845608028654f * (y + 0.044715f * y3)));
}

__device__ __forceinline__ float to_tf32(float x) {
    uint32_t y;
    asm("cvt.rna.tf32.f32 %0, %1;" : "=r"(y) : "f"(x));
    return __uint_as_float(y);
}

__device__ __forceinline__ void cp_async16(void* smem_dst, const void* gmem_src) {
    uint32_t s = (uint32_t)__cvta_generic_to_shared(smem_dst);
    asm volatile("cp.async.cg.shared.global [%0], [%1], 16;\n"
                 :: "r"(s), "l"(gmem_src));
}
__device__ __forceinline__ void cp_commit() {
    asm volatile("cp.async.commit_group;\n");
}
template <int N>
__device__ __forceinline__ void cp_wait() {
    asm volatile("cp.async.wait_group %0;\n" :: "n"(N));
}

__device__ __forceinline__ void mma_tf32(
    float& d0, float& d1, float& d2, float& d3,
    uint32_t a0, uint32_t a1, uint32_t a2, uint32_t a3,
    uint32_t b0, uint32_t b1)
{
    asm volatile(
        "mma.sync.aligned.m16n8k8.row.col.f32.tf32.tf32.f32 "
        "{%0,%1,%2,%3}, {%4,%5,%6,%7}, {%8,%9}, {%0,%1,%2,%3};"
        : "+f"(d0), "+f"(d1), "+f"(d2), "+f"(d3)
        : "r"(a0), "r"(a1), "r"(a2), "r"(a3), "r"(b0), "r"(b1));
}

// ---------------------------------------------------------------------------
// Kernel 0: round ALL weights to tf32 + permute K-dim rows, one launch.
// ---------------------------------------------------------------------------
__global__ void __launch_bounds__(256) round_weights_kernel(
    const float4* __restrict__ Wq, const float4* __restrict__ Wkv,
    const float4* __restrict__ Wo, const float4* __restrict__ W1,
    const float4* __restrict__ W2,
    float4* __restrict__ wqkv, float4* __restrict__ wo,
    float4* __restrict__ w1, float4* __restrict__ w2)
{
    const int t = blockIdx.y;
    const int i = blockIdx.x * 256 + threadIdx.x;
    const float4* src = nullptr;
    float4* dst = nullptr;
    int n4 = 0, di = 0;
    switch (t) {
        case 0: n4 = DMODEL * DMODEL / 4;     src = Wq;  dst = wqkv;
                di = kperm(i >> 8) * 768 + (i & 255); break;
        case 1: n4 = DMODEL * 2 * DMODEL / 4; src = Wkv; dst = wqkv;
                di = kperm(i >> 9) * 768 + 256 + (i & 511); break;
        case 2: n4 = DMODEL * DMODEL / 4;     src = Wo;  dst = wo;
                di = kperm(i >> 8) * 256 + (i & 255); break;
        case 3: n4 = DMODEL * MLPD / 4;       src = W1;  dst = w1;
                di = kperm(i >> 10) * 1024 + (i & 1023); break;
        case 4: n4 = MLPD * DMODEL / 4;       src = W2;  dst = w2;
                di = kperm(i >> 8) * 256 + (i & 255); break;
    }
    if (i < n4) {
        float4 v = src[i];
        v.x = to_tf32(v.x); v.y = to_tf32(v.y);
        v.z = to_tf32(v.z); v.w = to_tf32(v.w);
        dst[di] = v;
    }
}

// ---------------------------------------------------------------------------
// Kernel 1: mod = silu(c) @ Wada + bada        [4, 6144]
// ---------------------------------------------------------------------------
__global__ void __launch_bounds__(256) ada_mod_kernel(
    const float* __restrict__ c, const float* __restrict__ Wada,
    const float* __restrict__ bada, float* __restrict__ mod)
{
    __shared__ float sc[DMODEL];
    int b = blockIdx.y;
    int n = blockIdx.x * 256 + threadIdx.x;
    for (int i = threadIdx.x; i < DMODEL; i += 256) {
        float v = c[b * DMODEL + i];
        sc[i] = v / (1.0f + __expf(-v));
    }
    __syncthreads();
    float acc = 0.0f;
    const float* wp = Wada + n;
    for (int k = 0; k < DMODEL; k++)
        acc = fmaf(sc[k], wp[(size_t)k * SIXD], acc);
    mod[b * SIXD + n] = acc + bada[n];
}

// ---------------------------------------------------------------------------
// Kernel 2: out = tf32(LN(x) * (1 + scale) + shift), K-permuted store
// ---------------------------------------------------------------------------
__global__ void __launch_bounds__(256) ln_mod_kernel(
    const float* __restrict__ x, const float* __restrict__ mod,
    int shiftOff, int scaleOff, float* __restrict__ out)
{
    __shared__ float red[8];
    int row = blockIdx.x;
    int b = row >> 10;
    const float4* xr = (const float4*)(x + (size_t)row * DMODEL);
    float4 v = xr[threadIdx.x];

    float s = v.x + v.y + v.z + v.w;
    #pragma unroll
    for (int o = 16; o; o >>= 1) s += __shfl_xor_sync(0xffffffffu, s, o);
    if ((threadIdx.x & 31) == 0) red[threadIdx.x >> 5] = s;
    __syncthreads();
    float tot = 0.f;
    #pragma unroll
    for (int w = 0; w < 8; w++) tot += red[w];
    float mean = tot * (1.0f / DMODEL);
    __syncthreads();

    float dx = v.x - mean, dy = v.y - mean, dz = v.z - mean, dw = v.w - mean;
    float q = dx * dx + dy * dy + dz * dz + dw * dw;
    #pragma unroll
    for (int o = 16; o; o >>= 1) q += __shfl_xor_sync(0xffffffffu, q, o);
    if ((threadIdx.x & 31) == 0) red[threadIdx.x >> 5] = q;
    __syncthreads();
    float vtot = 0.f;
    #pragma unroll
    for (int w = 0; w < 8; w++) vtot += red[w];
    float rstd = rsqrtf(vtot * (1.0f / DMODEL) + EPS);

    int c0 = threadIdx.x * 4;
    const float* base = mod + (size_t)b * SIXD;
    float4 shv = *(const float4*)(base + shiftOff + c0);
    float4 scv = *(const float4*)(base + scaleOff + c0);
    float* orow = out + (size_t)row * DMODEL;
    orow[kperm(c0 + 0)] = to_tf32(dx * rstd * (1.0f + scv.x) + shv.x);
    orow[kperm(c0 + 1)] = to_tf32(dy * rstd * (1.0f + scv.y) + shv.y);
    orow[kperm(c0 + 2)] = to_tf32(dz * rstd * (1.0f + scv.z) + shv.z);
    orow[kperm(c0 + 3)] = to_tf32(dw * rstd * (1.0f + scv.w) + shv.w);
}

// ---------------------------------------------------------------------------
// Kernel 3: TF32 mma.sync GEMM, cp.async 3-stage pipeline, ONE sync/tile.
// 4 warps (128 threads), warp tile 64x64 (2m x 2n) -> half the LDS per mma.
// A and B K-permuted within groups of 8 (A fragments load as LDS.64).
//   EPI 1: C = tf32(gelu(acc + bias[n])), K-permuted store (feeds W2)
//   EPI 2: C = res + gate * (acc + bias[n])   (natural; exact fp32 residual)
//   EPI 3: qkv split (natural): cols<1024 -> C (+bias), else -> C2 (+bias2)
// ---------------------------------------------------------------------------
#define GSTAGES 3
#define APAD 40
#define BPAD 132
#define GEMM_SMEM_BYTES (GSTAGES * (128 * APAD + 32 * BPAD) * (int)sizeof(float))

template <int EPI>
__global__ void __launch_bounds__(128, 2) mma_gemm_kernel(
    const float* __restrict__ A, const float* __restrict__ B,
    const float* __restrict__ bias, const float* __restrict__ bias2,
    const float* __restrict__ res, const float* __restrict__ gate,
    float* __restrict__ C, float* __restrict__ C2,
    int M, int N, int K)
{
    extern __shared__ char smemRaw[];
    float (*As)[128][APAD] = reinterpret_cast<float(*)[128][APAD]>(smemRaw);
    float (*Bs)[32][BPAD]  = reinterpret_cast<float(*)[32][BPAD]>(
        smemRaw + GSTAGES * 128 * APAD * sizeof(float));

    const int tid  = threadIdx.x;
    const int lane = tid & 31;
    const int warp = tid >> 5;
    const int wm   = warp & 1;      // 2 m-bands of 64
    const int wn   = warp >> 1;     // 2 n-bands of 64
    const int bm   = blockIdx.y * 128;
    const int bn   = blockIdx.x * 128;

    const int g  = lane >> 2;
    const int tg = lane & 3;

    // loader indices (8 A chunks + 8 B chunks per thread per stage)
    const int aRow0 = tid >> 3;          // 0..15 (+16 per i)
    const int aK4   = (tid & 7) * 4;
    const int bK0   = tid >> 5;          // 0..3  (+4 per i)
    const int bN4   = (tid & 31) * 4;

    float acc[4][8][4];
    #pragma unroll
    for (int i = 0; i < 4; i++)
        #pragma unroll
        for (int j = 0; j < 8; j++)
            #pragma unroll
            for (int r = 0; r < 4; r++) acc[i][j][r] = 0.f;

    const int kTiles = K >> 5;

    auto load_tile = [&](int st, int k0) {
        #pragma unroll
        for (int i = 0; i < 8; i++) {
            int r = i * 16 + aRow0;
            cp_async16(&As[st][r][aK4], A + (size_t)(bm + r) * K + k0 + aK4);
        }
        #pragma unroll
        for (int i = 0; i < 8; i++) {
            int kk = i * 4 + bK0;
            cp_async16(&Bs[st][kk][bN4], B + (size_t)(k0 + kk) * N + bn + bN4);
        }
    };

    #pragma unroll
    for (int s = 0; s < GSTAGES - 1; s++) {
        load_tile(s, s * 32);
        cp_commit();
    }

    for (int it = 0; it < kTiles; it++) {
        cp_wait<GSTAGES - 2>();
        __syncthreads();

        int nxt = it + GSTAGES - 1;
        if (nxt < kTiles)
            load_tile(nxt % GSTAGES, nxt * 32);
        cp_commit();

        const int st = it % GSTAGES;
        #pragma unroll
        for (int ks = 0; ks < 4; ks++) {
            const int kb = ks * 8;
            uint32_t a[4][4], b[8][2];
            #pragma unroll
            for (int mf = 0; mf < 4; mf++) {
                int r = wm * 64 + mf * 16 + g;
                float2 av0 = *(const float2*)&As[st][r    ][kb + 2 * tg];
                float2 av1 = *(const float2*)&As[st][r + 8][kb + 2 * tg];
                a[mf][0] = __float_as_uint(av0.x);
                a[mf][1] = __float_as_uint(av1.x);
                a[mf][2] = __float_as_uint(av0.y);
                a[mf][3] = __float_as_uint(av1.y);
            }
            #pragma unroll
            for (int nf = 0; nf < 8; nf++) {
                int n = wn * 64 + nf * 8 + g;
                b[nf][0] = __float_as_uint(Bs[st][kb + 2 * tg    ][n]);
                b[nf][1] = __float_as_uint(Bs[st][kb + 2 * tg + 1][n]);
            }
            #pragma unroll
            for (int mf = 0; mf < 4; mf++)
                #pragma unroll
                for (int nf = 0; nf < 8; nf++)
                    mma_tf32(acc[mf][nf][0], acc[mf][nf][1],
                             acc[mf][nf][2], acc[mf][nf][3],
                             a[mf][0], a[mf][1], a[mf][2], a[mf][3],
                             b[nf][0], b[nf][1]);
        }
    }

    #pragma unroll
    for (int mf = 0; mf < 4; mf++) {
        #pragma unroll
        for (int half = 0; half < 2; half++) {
            int row = bm + wm * 64 + mf * 16 + g + half * 8;
            size_t gbase = (size_t)(row >> 10) * SIXD;
            #pragma unroll
            for (int nf = 0; nf < 8; nf++) {
                int col = bn + wn * 64 + nf * 8 + 2 * tg;
                float y0 = acc[mf][nf][half * 2 + 0];
                float y1 = acc[mf][nf][half * 2 + 1];
                if (EPI == 3) {
                    if (col < DMODEL) {
                        size_t rb = (size_t)row * DMODEL;
                        C[rb + col]     = to_tf32(y0 + bias[col]);
                        C[rb + col + 1] = to_tf32(y1 + bias[col + 1]);
                    } else {
                        int c2 = col - DMODEL;
                        size_t rb = (size_t)row * (2 * DMODEL);
                        C2[rb + c2]     = to_tf32(y0 + bias2[c2]);
                        C2[rb + c2 + 1] = to_tf32(y1 + bias2[c2 + 1]);
                    }
                } else if (EPI == 1) {
                    size_t rbase = (size_t)row * N;
                    C[rbase + kperm(col)]     = to_tf32(gelu_tanh(y0 + bias[col]));
                    C[rbase + kperm(col + 1)] = to_tf32(gelu_tanh(y1 + bias[col + 1]));
                } else {
                    size_t rbase = (size_t)row * N;
                    y0 = res[rbase + col]     + gate[gbase + col]     * (y0 + bias[col]);
                    y1 = res[rbase + col + 1] + gate[gbase + col + 1] * (y1 + bias[col + 1]);
                    C[rbase + col]     = y0;
                    C[rbase + col + 1] = y1;
                }
            }
        }
    }
}

// ---------------------------------------------------------------------------
// Kernel 4: flash attention on tf32 tensor cores
// 8 warps x m16 = 128 q rows per block, Bc=64, d=64.
// Output store is K-permuted (att feeds the Wo GEMM as A).
// ---------------------------------------------------------------------------
#define AQ_PAD 68
#define AK_PAD 68
#define AV_PAD 72
#define AP_PAD 68
#define ATTN_SMEM_BYTES ((128 * AQ_PAD + 64 * AK_PAD + 64 * AV_PAD + 128 * AP_PAD) * (int)sizeof(float))

__global__ void __launch_bounds__(256, 2) attn_mma_kernel(
    const float* __restrict__ q, const float* __restrict__ kv,
    float* __restrict__ out)
{
    extern __shared__ float sm[];
    float (*Qs)[AQ_PAD] = reinterpret_cast<float(*)[AQ_PAD]>(sm);
    float (*Ks)[AK_PAD] = reinterpret_cast<float(*)[AK_PAD]>(sm + 128 * AQ_PAD);
    float (*Vs)[AV_PAD] = reinterpret_cast<float(*)[AV_PAD]>(sm + 128 * AQ_PAD + 64 * AK_PAD);
    float (*Ps)[AP_PAD] = reinterpret_cast<float(*)[AP_PAD]>(sm + 128 * AQ_PAD + 64 * AK_PAD + 64 * AV_PAD);

    const int tid  = threadIdx.x;
    const int lane = tid & 31;
    const int warp = tid >> 5;
    const int g    = lane >> 2;
    const int tg   = lane & 3;
    const int b    = blockIdx.y >> 4;
    const int h    = blockIdx.y & 15;
    const int q0   = blockIdx.x * 128;
    const int rg   = warp * 16 + g;

    for (int t = tid; t < 128 * 16; t += 256) {
        int r = t >> 4, d4 = (t & 15) * 4;
        float4 v = *(const float4*)(q +
            ((((size_t)(b * NTOK + q0 + r)) * HEADS + h) << 6) + d4);
        Qs[r][d4 + 0] = v.x * 0.125f; Qs[r][d4 + 1] = v.y * 0.125f;
        Qs[r][d4 + 2] = v.z * 0.125f; Qs[r][d4 + 3] = v.w * 0.125f;
    }

    float o[8][4];
    #pragma unroll
    for (int nf = 0; nf < 8; nf++)
        #pragma unroll
        for (int r = 0; r < 4; r++) o[nf][r] = 0.f;
    float m0 = -INFINITY, m1 = -INFINITY, l0 = 0.f, l1 = 0.f;

    for (int jt = 0; jt < NTOK / 64; jt++) {
        int j0 = jt * 64;
        __syncthreads();
        for (int t = tid; t < 64 * 16; t += 256) {
            int r = t >> 4, d4 = (t & 15) * 4;
            size_t base = (size_t)(b * NTOK + j0 + r) * (2 * DMODEL) + h * HDIM + d4;
            float4 kvec = *(const float4*)(kv + base);
            float4 vvec = *(const float4*)(kv + base + DMODEL);
            Ks[r][d4 + 0] = kvec.x; Ks[r][d4 + 1] = kvec.y;
            Ks[r][d4 + 2] = kvec.z; Ks[r][d4 + 3] = kvec.w;
            Vs[r][d4 + 0] = vvec.x; Vs[r][d4 + 1] = vvec.y;
            Vs[r][d4 + 2] = vvec.z; Vs[r][d4 + 3] = vvec.w;
        }
        __syncthreads();

        float s[8][4];
        #pragma unroll
        for (int nf = 0; nf < 8; nf++)
            #pragma unroll
            for (int r = 0; r < 4; r++) s[nf][r] = 0.f;
        #pragma unroll
        for (int kb = 0; kb < 64; kb += 8) {
            uint32_t a0 = __float_as_uint(Qs[rg    ][kb + tg    ]);
            uint32_t a1 = __float_as_uint(Qs[rg + 8][kb + tg    ]);
            uint32_t a2 = __float_as_uint(Qs[rg    ][kb + tg + 4]);
            uint32_t a3 = __float_as_uint(Qs[rg + 8][kb + tg + 4]);
            #pragma unroll
            for (int nf = 0; nf < 8; nf++) {
                uint32_t b0 = __float_as_uint(Ks[nf * 8 + g][kb + tg    ]);
                uint32_t b1 = __float_as_uint(Ks[nf * 8 + g][kb + tg + 4]);
                mma_tf32(s[nf][0], s[nf][1], s[nf][2], s[nf][3],
                         a0, a1, a2, a3, b0, b1);
            }
        }

        float mx0 = -INFINITY, mx1 = -INFINITY;
        #pragma unroll
        for (int nf = 0; nf < 8; nf++) {
            mx0 = fmaxf(mx0, fmaxf(s[nf][0], s[nf][1]));
            mx1 = fmaxf(mx1, fmaxf(s[nf][2], s[nf][3]));
        }
        mx0 = fmaxf(mx0, __shfl_xor_sync(0xffffffffu, mx0, 1));
        mx0 = fmaxf(mx0, __shfl_xor_sync(0xffffffffu, mx0, 2));
        mx1 = fmaxf(mx1, __shfl_xor_sync(0xffffffffu, mx1, 1));
        mx1 = fmaxf(mx1, __shfl_xor_sync(0xffffffffu, mx1, 2));
        float mN0 = fmaxf(m0, mx0), mN1 = fmaxf(m1, mx1);
        float c0 = __expf(m0 - mN0), c1 = __expf(m1 - mN1);
        float sum0 = 0.f, sum1 = 0.f;
        #pragma unroll
        for (int nf = 0; nf < 8; nf++) {
            s[nf][0] = __expf(s[nf][0] - mN0); sum0 += s[nf][0];
            s[nf][1] = __expf(s[nf][1] - mN0); sum0 += s[nf][1];
            s[nf][2] = __expf(s[nf][2] - mN1); sum1 += s[nf][2];
            s[nf][3] = __expf(s[nf][3] - mN1); sum1 += s[nf][3];
        }
        sum0 += __shfl_xor_sync(0xffffffffu, sum0, 1);
        sum0 += __shfl_xor_sync(0xffffffffu, sum0, 2);
        sum1 += __shfl_xor_sync(0xffffffffu, sum1, 1);
        sum1 += __shfl_xor_sync(0xffffffffu, sum1, 2);
        l0 = l0 * c0 + sum0; l1 = l1 * c1 + sum1;
        m0 = mN0; m1 = mN1;
        #pragma unroll
        for (int nf = 0; nf < 8; nf++) {
            o[nf][0] *= c0; o[nf][1] *= c0;
            o[nf][2] *= c1; o[nf][3] *= c1;
        }

        #pragma unroll
        for (int nf = 0; nf < 8; nf++) {
            int col = nf * 8 + 2 * tg;
            Ps[rg    ][col] = to_tf32(s[nf][0]); Ps[rg    ][col + 1] = to_tf32(s[nf][1]);
            Ps[rg + 8][col] = to_tf32(s[nf][2]); Ps[rg + 8][col + 1] = to_tf32(s[nf][3]);
        }
        __syncwarp();

        #pragma unroll
        for (int kb = 0; kb < 64; kb += 8) {
            uint32_t a0 = __float_as_uint(Ps[rg    ][kb + tg    ]);
            uint32_t a1 = __float_as_uint(Ps[rg + 8][kb + tg    ]);
            uint32_t a2 = __float_as_uint(Ps[rg    ][kb + tg + 4]);
            uint32_t a3 = __float_as_uint(Ps[rg + 8][kb + tg + 4]);
            #pragma unroll
            for (int nf = 0; nf < 8; nf++) {
                uint32_t b0 = __float_as_uint(Vs[kb + tg    ][nf * 8 + g]);
                uint32_t b1 = __float_as_uint(Vs[kb + tg + 4][nf * 8 + g]);
                mma_tf32(o[nf][0], o[nf][1], o[nf][2], o[nf][3],
                         a0, a1, a2, a3, b0, b1);
            }
        }
    }

    float inv0 = 1.0f / l0, inv1 = 1.0f / l1;
    size_t row0 = ((((size_t)(b * NTOK + q0 + rg)) * HEADS + h) << 6);
    size_t row1 = ((((size_t)(b * NTOK + q0 + rg + 8)) * HEADS + h) << 6);
    #pragma unroll
    for (int nf = 0; nf < 8; nf++) {
        int col = nf * 8 + 2 * tg;
        out[row0 + kperm(col)]     = to_tf32(o[nf][0] * inv0);
        out[row0 + kperm(col + 1)] = to_tf32(o[nf][1] * inv0);
        out[row1 + kperm(col)]     = to_tf32(o[nf][2] * inv1);
        out[row1 + kperm(col + 1)] = to_tf32(o[nf][3] * inv1);
    }
}

// ---------------------------------------------------------------------------
// Launch
// ---------------------------------------------------------------------------
extern "C" void kernel_launch(void* const* d_in, const int* in_sizes, int n_in,
                              void* d_out, int out_size)
{
    const float* x    = (const float*)d_in[0];
    const float* c    = (const float*)d_in[1];
    const float* Wq   = (const float*)d_in[2];
    const float* bq   = (const float*)d_in[3];
    const float* Wkv  = (const float*)d_in[4];
    const float* bkv  = (const float*)d_in[5];
    const float* Wo   = (const float*)d_in[6];
    const float* bo   = (const float*)d_in[7];
    const float* W1   = (const float*)d_in[8];
    const float* b1   = (const float*)d_in[9];
    const float* W2   = (const float*)d_in[10];
    const float* b2   = (const float*)d_in[11];
    const float* Wada = (const float*)d_in[12];
    const float* bada = (const float*)d_in[13];
    float* out = (float*)d_out;

    float *mod, *h, *q, *kv, *att, *m1, *wqkv, *wo, *w1, *w2;
    cudaGetSymbolAddress((void**)&mod,  g_mod);
    cudaGetSymbolAddress((void**)&h,    g_h);
    cudaGetSymbolAddress((void**)&q,    g_q);
    cudaGetSymbolAddress((void**)&kv,   g_kv);
    cudaGetSymbolAddress((void**)&att,  g_att);
    cudaGetSymbolAddress((void**)&m1,   g_m1);
    cudaGetSymbolAddress((void**)&wqkv, g_wqkv);
    cudaGetSymbolAddress((void**)&wo,   g_wo);
    cudaGetSymbolAddress((void**)&w1,   g_w1);
    cudaGetSymbolAddress((void**)&w2,   g_w2);

    cudaFuncSetAttribute(attn_mma_kernel,
                         cudaFuncAttributeMaxDynamicSharedMemorySize, ATTN_SMEM_BYTES);
    cudaFuncSetAttribute(mma_gemm_kernel<1>,
                         cudaFuncAttributeMaxDynamicSharedMemorySize, GEMM_SMEM_BYTES);
    cudaFuncSetAttribute(mma_gemm_kernel<2>,
                         cudaFuncAttributeMaxDynamicSharedMemorySize, GEMM_SMEM_BYTES);
    cudaFuncSetAttribute(mma_gemm_kernel<3>,
                         cudaFuncAttributeMaxDynamicSharedMemorySize, GEMM_SMEM_BYTES);

    // 0) round + row-permute all weights (one launch)
    round_weights_kernel<<<dim3(DMODEL * MLPD / 4 / 256, 5), 256>>>(
        (const float4*)Wq, (const float4*)Wkv, (const float4*)Wo,
        (const float4*)W1, (const float4*)W2,
        (float4*)wqkv, (float4*)wo, (float4*)w1, (float4*)w2);

    // 1) adaLN modulation
    ada_mod_kernel<<<dim3(SIXD / 256, BATCH), 256>>>(c, Wada, bada, mod);

    // 2) h = tf32(modulate(LN(x), sh_msa, sc_msa)), K-permuted
    ln_mod_kernel<<<ROWS, 256>>>(x, mod, 0 * DMODEL, 1 * DMODEL, h);

    // 3) fused QKV GEMM: [q | kv] = h @ [Wq | Wkv] + [bq | bkv]  (natural out)
    mma_gemm_kernel<3><<<dim3(3 * DMODEL / 128, ROWS / 128), 128, GEMM_SMEM_BYTES>>>(
        h, wqkv, bq, bkv, nullptr, nullptr, q, kv, ROWS, 3 * DMODEL, DMODEL);

    // 4) attention (tensor-core flash; K-permuted att out)
    attn_mma_kernel<<<dim3(NTOK / 128, BATCH * HEADS), 256, ATTN_SMEM_BYTES>>>(q, kv, att);

    // 5) x1 = x + g_msa * (att @ Wo + bo)   -> d_out (natural)
    mma_gemm_kernel<2><<<dim3(DMODEL / 128, ROWS / 128), 128, GEMM_SMEM_BYTES>>>(
        att, wo, bo, nullptr, x, mod + 2 * DMODEL, out, nullptr, ROWS, DMODEL, DMODEL);

    // 6) h2 = tf32(modulate(LN(x1), sh_mlp, sc_mlp)), K-permuted
    ln_mod_kernel<<<ROWS, 256>>>(out, mod, 3 * DMODEL, 4 * DMODEL, h);

    // 7) m1 = tf32(gelu(h2 @ W1 + b1)), K-permuted store
    mma_gemm_kernel<1><<<dim3(MLPD / 128, ROWS / 128), 128, GEMM_SMEM_BYTES>>>(
        h, w1, b1, nullptr, nullptr, nullptr, m1, nullptr, ROWS, MLPD, DMODEL);

    // 8) x2 = x1 + g_mlp * (m1 @ W2 + b2)   -> d_out (natural)
    mma_gemm_kernel<2><<<dim3(DMODEL / 128, ROWS / 128), 128, GEMM_SMEM_BYTES>>>(
        m1, w2, b2, nullptr, out, mod + 5 * DMODEL, out, nullptr, ROWS, DMODEL, MLPD);
}